// round 8
// baseline (speedup 1.0000x reference)
#include <cuda_runtime.h>
#include <cuda_bf16.h>
#include <cstdint>

#define B_ 128
#define T_ 128
#define D_ 2048
#define U_ 512

// ================= device scratch =================
__device__ float g_xproj[(size_t)B_ * T_ * U_];          // 32 MB
__device__ float g_H[2][B_ * U_];                        // ping-pong pre-normalized state
__device__ float g_psum[2][B_ * 16];
__device__ float g_psq[2][B_ * 16];
__device__ int   g_bar[16];
// bf16 hi/lo planes for the tensor-core GEMM
__device__ __nv_bfloat16 g_Ahi[(size_t)16384 * 2048];    // 64 MB
__device__ __nv_bfloat16 g_Alo[(size_t)16384 * 2048];    // 64 MB
__device__ __nv_bfloat16 g_Bhi[(size_t)512 * 2048];      // 2 MB (w_in^T)
__device__ __nv_bfloat16 g_Blo[(size_t)512 * 2048];      // 2 MB

// ================= helpers =================
__device__ __forceinline__ uint32_t smem_u32(const void* p) {
    uint32_t a;
    asm("{ .reg .u64 t; cvta.to.shared.u64 t, %1; cvt.u32.u64 %0, t; }" : "=r"(a) : "l"(p));
    return a;
}
__device__ __forceinline__ void cp_async16(uint32_t dst, const void* src) {
    asm volatile("cp.async.cg.shared.global [%0], [%1], 16;" :: "r"(dst), "l"(src) : "memory");
}
__device__ __forceinline__ void ldmatrix_x4(uint32_t& d0, uint32_t& d1, uint32_t& d2, uint32_t& d3,
                                            uint32_t addr) {
    asm volatile("ldmatrix.sync.aligned.m8n8.x4.shared.b16 {%0,%1,%2,%3}, [%4];"
                 : "=r"(d0), "=r"(d1), "=r"(d2), "=r"(d3) : "r"(addr));
}
__device__ __forceinline__ void mma16816(float* c, const uint32_t* a, const uint32_t* b) {
    asm volatile("mma.sync.aligned.m16n8k16.row.col.f32.bf16.bf16.f32 "
                 "{%0,%1,%2,%3}, {%4,%5,%6,%7}, {%8,%9}, {%0,%1,%2,%3};"
                 : "+f"(c[0]), "+f"(c[1]), "+f"(c[2]), "+f"(c[3])
                 : "r"(a[0]), "r"(a[1]), "r"(a[2]), "r"(a[3]), "r"(b[0]), "r"(b[1]));
}

// ================= conv: x -> hi/lo bf16 planes (row-major, K=2048) =================
__global__ void __launch_bounds__(256) conv_x(const float* __restrict__ x) {
    const size_t i = (size_t)blockIdx.x * 256 + threadIdx.x;
    const size_t e0 = i * 8;
    float4 v0 = *(const float4*)(x + e0);
    float4 v1 = *(const float4*)(x + e0 + 4);
    float v[8] = {v0.x, v0.y, v0.z, v0.w, v1.x, v1.y, v1.z, v1.w};
    unsigned short hs[8], ls[8];
#pragma unroll
    for (int j = 0; j < 8; j++) {
        __nv_bfloat16 h = __float2bfloat16(v[j]);
        __nv_bfloat16 l = __float2bfloat16(v[j] - __bfloat162float(h));
        hs[j] = __bfloat16_as_ushort(h);
        ls[j] = __bfloat16_as_ushort(l);
    }
    uint4 ph, pl;
    ph.x = hs[0] | ((uint32_t)hs[1] << 16); ph.y = hs[2] | ((uint32_t)hs[3] << 16);
    ph.z = hs[4] | ((uint32_t)hs[5] << 16); ph.w = hs[6] | ((uint32_t)hs[7] << 16);
    pl.x = ls[0] | ((uint32_t)ls[1] << 16); pl.y = ls[2] | ((uint32_t)ls[3] << 16);
    pl.z = ls[4] | ((uint32_t)ls[5] << 16); pl.w = ls[6] | ((uint32_t)ls[7] << 16);
    *(uint4*)(g_Ahi + e0) = ph;
    *(uint4*)(g_Alo + e0) = pl;
}

// ================= conv: w_in [2048][512] -> w^T hi/lo [512][2048] =================
__global__ void __launch_bounds__(256) conv_w(const float* __restrict__ w) {
    __shared__ float ts[32][33];
    const int tid = threadIdx.x;
    const int bu = blockIdx.x;
    const int bd = blockIdx.y;
    const int tx = tid & 31, ty = tid >> 5;
#pragma unroll
    for (int j = 0; j < 4; j++) {
        const int dl = ty + 8 * j;
        ts[dl][tx] = w[(size_t)(bd * 32 + dl) * U_ + bu * 32 + tx];
    }
    __syncthreads();
    const int ul = tid >> 3, kg = (tid & 7) * 4;
    const int u = bu * 32 + ul;
    const int kk = bd * 32 + kg;
    unsigned short hs[4], ls[4];
#pragma unroll
    for (int j = 0; j < 4; j++) {
        const float vv = ts[kg + j][ul];
        __nv_bfloat16 h = __float2bfloat16(vv);
        __nv_bfloat16 l = __float2bfloat16(vv - __bfloat162float(h));
        hs[j] = __bfloat16_as_ushort(h);
        ls[j] = __bfloat16_as_ushort(l);
    }
    uint2 ph, pl;
    ph.x = hs[0] | ((uint32_t)hs[1] << 16); ph.y = hs[2] | ((uint32_t)hs[3] << 16);
    pl.x = ls[0] | ((uint32_t)ls[1] << 16); pl.y = ls[2] | ((uint32_t)ls[3] << 16);
    *(uint2*)(g_Bhi + (size_t)u * D_ + kk) = ph;
    *(uint2*)(g_Blo + (size_t)u * D_ + kk) = pl;
}

// ================= mma.sync GEMM: xproj = X@W + bias =================
__global__ void __launch_bounds__(256, 2) gemm_mma(const float* __restrict__ bias) {
    extern __shared__ char sm[];
    const uint32_t sb = smem_u32(sm);
    const int tid = threadIdx.x, lane = tid & 31, wid = tid >> 5;
    const int wm = wid & 3, wn = wid >> 2;
    const int bn = blockIdx.x, bm = blockIdx.y;

    float acc[2][8][4];
#pragma unroll
    for (int mi = 0; mi < 2; mi++)
#pragma unroll
        for (int nj = 0; nj < 8; nj++)
#pragma unroll
            for (int e = 0; e < 4; e++) acc[mi][nj][e] = 0.f;

    auto load_stage = [&](int s, int kch) {
        const int seg = kch >> 5, ck = kch & 31;
        const __nv_bfloat16* Ab = (seg < 2) ? g_Ahi : g_Alo;
        const __nv_bfloat16* Bb = (seg == 1) ? g_Blo : g_Bhi;
        const uint32_t sA = sb + s * 32768;
        const uint32_t sB = sA + 16384;
#pragma unroll
        for (int i = 0; i < 4; i++) {
            const int cid = tid + 256 * i;
            const int r = cid >> 3, c = cid & 7;
            const uint32_t sw = (uint32_t)((c ^ (r & 7)) << 4);
            cp_async16(sA + r * 128 + sw,
                       Ab + (size_t)(bm * 128 + r) * D_ + ck * 64 + c * 8);
            cp_async16(sB + r * 128 + sw,
                       Bb + (size_t)(bn * 128 + r) * D_ + ck * 64 + c * 8);
        }
    };

    load_stage(0, 0);
    asm volatile("cp.async.commit_group;" ::: "memory");
    load_stage(1, 1);
    asm volatile("cp.async.commit_group;" ::: "memory");

    for (int k = 0; k < 96; k++) {
        asm volatile("cp.async.wait_group 1;" ::: "memory");
        __syncthreads();
        if (k + 2 < 96) load_stage((k + 2) % 3, k + 2);
        asm volatile("cp.async.commit_group;" ::: "memory");

        const uint32_t sA = sb + (k % 3) * 32768;
        const uint32_t sB = sA + 16384;
#pragma unroll
        for (int kk = 0; kk < 4; kk++) {
            uint32_t aF[2][4];
#pragma unroll
            for (int mi = 0; mi < 2; mi++) {
                const int row = wm * 32 + mi * 16 + (lane & 15);
                const int ch = kk * 2 + (lane >> 4);
                ldmatrix_x4(aF[mi][0], aF[mi][1], aF[mi][2], aF[mi][3],
                            sA + row * 128 + ((ch ^ (row & 7)) << 4));
            }
            uint32_t bF[8][2];
#pragma unroll
            for (int ni = 0; ni < 4; ni++) {
                const int row = wn * 64 + ni * 16 + (lane & 7) + ((lane & 16) >> 1);
                const int ch = kk * 2 + ((lane & 8) >> 3);
                uint32_t r0, r1, r2, r3;
                ldmatrix_x4(r0, r1, r2, r3, sB + row * 128 + ((ch ^ (row & 7)) << 4));
                bF[2 * ni][0] = r0; bF[2 * ni][1] = r1;
                bF[2 * ni + 1][0] = r2; bF[2 * ni + 1][1] = r3;
            }
#pragma unroll
            for (int mi = 0; mi < 2; mi++)
#pragma unroll
                for (int nj = 0; nj < 8; nj++)
                    mma16816(acc[mi][nj], aF[mi], bF[nj]);
        }
    }

#pragma unroll
    for (int mi = 0; mi < 2; mi++) {
        const int row = bm * 128 + wm * 32 + mi * 16 + (lane >> 2);
#pragma unroll
        for (int nj = 0; nj < 8; nj++) {
            const int col = bn * 128 + wn * 64 + nj * 8 + (lane & 3) * 2;
            const float2 bi = *(const float2*)&bias[col];
            float2 v0, v1;
            v0.x = acc[mi][nj][0] + bi.x;
            v0.y = acc[mi][nj][1] + bi.y;
            v1.x = acc[mi][nj][2] + bi.x;
            v1.y = acc[mi][nj][3] + bi.y;
            *(float2*)&g_xproj[(size_t)row * U_ + col] = v0;
            *(float2*)&g_xproj[(size_t)(row + 8) * U_ + col] = v1;
        }
    }
}

// ================= scan: 512 threads, 16-way k-split, stats fused into load =================
// step t writes {g_H, g_psum, g_psq}[pw]; step t+1 reads all three at its pr (== prev pw).
// dyn smem (floats): sH[8][512] @0 | sPart[16][8][64] @4096 | sGB[2][512] @12288 = 13312 f
#define OFF_H    0
#define OFF_PART 4096
#define OFF_GB   12288
#define SCAN_SMEM (13312 * 4)

__global__ void __launch_bounds__(512, 1) liquid_scan(const float* __restrict__ wrec,
                                                      const float* __restrict__ tau,
                                                      const float* __restrict__ gamma,
                                                      const float* __restrict__ beta,
                                                      float* __restrict__ out) {
    extern __shared__ float S[];

    const int tid = threadIdx.x;
    const int lane = tid & 31;
    const int warp = tid >> 5;            // 0..15: k-split (32 k each)
    const int bblk = blockIdx.x >> 3;
    const int cblk = blockIdx.x & 7;
    const int rb = bblk * 8;
    const int cb = cblk * 64;
    const int c0 = lane * 2;              // GEMM phase: 2 cols/thread

    // reduce-phase mapping: 1 col/thread
    const int r_red = warp >> 1;          // row 0..7
    const int half = warp & 1;            // col half
    const int cR = half * 32 + lane;      // col within [0,64)
    const int b_own = rb + r_red;

    // w_rec slice: k in [warp*32, warp*32+32), cols cb+c0, cb+c0+1
    float2 wreg[32];
    {
        const int kb = warp * 32;
#pragma unroll
        for (int i = 0; i < 32; i++)
            wreg[i] = *(const float2*)&wrec[(size_t)(kb + i) * U_ + cb + c0];
    }
    const float tauR = tau[cb + cR];
    const float gamR = gamma[cb + cR];
    const float betR = beta[cb + cR];
    for (int i = tid; i < U_; i += 512) {
        S[OFF_GB + i] = gamma[i];
        S[OFF_GB + U_ + i] = beta[i];
    }

    int nbar = 0;
    float ns = 0.f;

    for (int t = 0; t < T_; t++) {
        const int pr = t & 1;
        const int pw = pr ^ 1;

        // ---- load h (LDG first), stats reduced under the LDG latency, then normalize ----
        if (t == 0) {
#pragma unroll
            for (int i = 0; i < 2; i++)
                *(float4*)&S[OFF_H + (tid + i * 512) * 4] = make_float4(0.f, 0.f, 0.f, 0.f);
        } else {
            const int rl = warp >> 1;
            const int k4b = (warp & 1) * 64 + lane;   // 2 float4 per thread (stride 32)
            const float4* Hg = (const float4*)g_H[pr];
            float4 hv0 = __ldcg(&Hg[(size_t)(rb + rl) * 128 + k4b]);
            float4 hv1 = __ldcg(&Hg[(size_t)(rb + rl) * 128 + k4b + 32]);
            // stats for row rl from the 16 partials published by step t-1 (plane pr)
            float v = 0.f;
            if (lane < 16) v = __ldcg(&g_psum[pr][(rb + rl) * 16 + lane]);
            else v = __ldcg(&g_psq[pr][(rb + rl) * 16 + (lane - 16)]);
#pragma unroll
            for (int o = 8; o > 0; o >>= 1) v += __shfl_xor_sync(0xffffffffu, v, o);
            const float s = __shfl_sync(0xffffffffu, v, 0);
            const float q = __shfl_sync(0xffffffffu, v, 16);
            const float mean = s * (1.f / 512.f);
            const float var = q * (1.f / 512.f) - mean * mean;
            const float rstd = rsqrtf(var + 1e-3f);
            float4* dst = (float4*)&S[OFF_H + rl * U_];
#pragma unroll
            for (int i = 0; i < 2; i++) {
                float4 hv = i ? hv1 : hv0;
                const int k4 = k4b + i * 32;
                const int c = k4 * 4;
                hv.x = S[OFF_GB + c + 0] * (hv.x - mean) * rstd + S[OFF_GB + U_ + c + 0];
                hv.y = S[OFF_GB + c + 1] * (hv.y - mean) * rstd + S[OFF_GB + U_ + c + 1];
                hv.z = S[OFF_GB + c + 2] * (hv.z - mean) * rstd + S[OFF_GB + U_ + c + 2];
                hv.w = S[OFF_GB + c + 3] * (hv.w - mean) * rstd + S[OFF_GB + U_ + c + 3];
                dst[k4] = hv;
            }
        }
        // prefetch xp for reduce phase (1 col/thread)
        const float xp = __ldg(&g_xproj[((size_t)b_own * T_ + t) * U_ + cb + cR]);
        __syncthreads();

        // ---- partial GEMM over this warp's 32-k slice (8 rows x 2 cols) ----
        float2 acc[8];
#pragma unroll
        for (int r = 0; r < 8; r++) acc[r] = make_float2(0.f, 0.f);
        {
            const float4* sH4 = (const float4*)&S[OFF_H];
            const int kb4 = warp * 8;
#pragma unroll
            for (int i4 = 0; i4 < 8; i4++) {
                float4 h[8];
#pragma unroll
                for (int r = 0; r < 8; r++) h[r] = sH4[r * 128 + kb4 + i4];
#pragma unroll
                for (int kkk = 0; kkk < 4; kkk++) {
                    const float2 wv = wreg[i4 * 4 + kkk];
#pragma unroll
                    for (int r = 0; r < 8; r++) {
                        const float hv = ((const float*)&h[r])[kkk];
                        acc[r].x += hv * wv.x;
                        acc[r].y += hv * wv.y;
                    }
                }
            }
        }
#pragma unroll
        for (int r = 0; r < 8; r++)
            *(float2*)&S[OFF_PART + (warp * 8 + r) * 64 + c0] = acc[r];
        __syncthreads();

        // ---- k-reduce (16 partials) + liquid update; publish to plane pw ----
        {
            float red = 0.f;
#pragma unroll
            for (int kw = 0; kw < 16; kw++)
                red += S[OFF_PART + (kw * 8 + r_red) * 64 + cR];
            const float base = red + xp;
            const float h0 = S[OFF_H + r_red * U_ + cb + cR];
            const float sg = 1.f / (1.f + __expf(-base));
            const float lt = tauR * sg + 1e-7f;
            ns = h0 + (base - h0) * lt;
            float s = ns;
            float q = ns * ns;
#pragma unroll
            for (int o = 16; o > 0; o >>= 1) {
                s += __shfl_xor_sync(0xffffffffu, s, o);
                q += __shfl_xor_sync(0xffffffffu, q, o);
            }
            g_H[pw][(size_t)b_own * U_ + cb + cR] = ns;
            if (lane == 0) {
                g_psum[pw][b_own * 16 + cblk * 2 + half] = s;
                g_psq[pw][b_own * 16 + cblk * 2 + half] = q;
            }
        }

        // ---- one global barrier per step ----
        __threadfence();
        __syncthreads();
        nbar++;
        if (tid == 0) {
            atomicAdd(&g_bar[bblk], 1);
            while (*(volatile int*)&g_bar[bblk] < 8 * nbar) { }
        }
        __syncthreads();
    }

    // ---- final output: last step (t=T_-1) published into plane pw = ((T_-1)&1)^1 = 0 ----
    {
        const int pL = ((T_ - 1) & 1) ^ 1;
        float v = 0.f;
        if (lane < 16) v = __ldcg(&g_psum[pL][b_own * 16 + lane]);
        else v = __ldcg(&g_psq[pL][b_own * 16 + (lane - 16)]);
#pragma unroll
        for (int o = 8; o > 0; o >>= 1) v += __shfl_xor_sync(0xffffffffu, v, o);
        const float s = __shfl_sync(0xffffffffu, v, 0);
        const float q = __shfl_sync(0xffffffffu, v, 16);
        const float mean = s * (1.f / 512.f);
        const float var = q * (1.f / 512.f) - mean * mean;
        const float rstd = rsqrtf(var + 1e-3f);
        out[(size_t)b_own * U_ + cb + cR] = gamR * (ns - mean) * rstd + betR;
    }
}

// ================= launch =================
extern "C" void kernel_launch(void* const* d_in, const int* in_sizes, int n_in,
                              void* d_out, int out_size) {
    const float* x     = (const float*)d_in[0];
    const float* w_in  = (const float*)d_in[1];
    const float* w_rec = (const float*)d_in[2];
    const float* bias  = (const float*)d_in[3];
    const float* tau   = (const float*)d_in[4];
    const float* gamma = (const float*)d_in[5];
    const float* beta  = (const float*)d_in[6];
    float* out = (float*)d_out;

    void* pBar = nullptr;
    cudaGetSymbolAddress(&pBar, g_bar);
    cudaMemsetAsync(pBar, 0, sizeof(int) * 16);

    static int attr_set = 0;
    if (!attr_set) {
        cudaFuncSetAttribute(gemm_mma, cudaFuncAttributeMaxDynamicSharedMemorySize, 98304);
        cudaFuncSetAttribute(liquid_scan, cudaFuncAttributeMaxDynamicSharedMemorySize, SCAN_SMEM);
        attr_set = 1;
    }

    conv_x<<<16384, 256>>>(x);
    conv_w<<<dim3(16, 64), 256>>>(w_in);
    gemm_mma<<<dim3(4, 128), 256, 98304>>>(bias);
    liquid_scan<<<128, 512, SCAN_SMEM>>>(w_rec, tau, gamma, beta, out);
}